// round 4
// baseline (speedup 1.0000x reference)
#include <cuda_runtime.h>
#include <cuda_bf16.h>

// Problem shape (fixed by the dataset): B=1, H=32, L=8192, D=128
#define H_DIM 32
#define L_DIM 8192
#define ROWS  (H_DIM * L_DIM)          // 262144 rows per tensor
#define GLOBAL_TOKENS 4
#define NBLOCKS (ROWS / 16)            // 16384 blocks, 8 warps x 2 rows each

// Output layout (float32, flattened in reference return order)
#define OFF_K    0ull
#define OFF_V    33554432ull
#define OFF_NINS 67108864ull
#define OFF_POS  67108896ull
#define OFF_KQ   67371040ull
#define OFF_KS   100925472ull
#define OFF_KZ   101187616ull
#define OFF_VQ   101449760ull
#define OFF_VS   135004192ull
#define OFF_VZ   135266336ull

// Per-head argmin scratch. We store ~((orderable_score << 32) | token_idx)
// and take atomicMax: max of complement == lexicographic min of (score, idx),
// i.e. jnp.argmin first-occurrence semantics. Max-identity is 0 => zero-init
// is the correct initial state; the last block resets slots to 0 after
// consuming them so every graph replay starts clean.
// 128B-strided slots: one L2 line / LTS slice per head.
__device__ unsigned long long g_argmax[H_DIM * 16];
__device__ unsigned int       g_count;          // block-completion counter

// Map float -> uint such that uint ascending order == float ascending order.
__device__ __forceinline__ unsigned int float_orderable(float f) {
    unsigned int b = __float_as_uint(f);
    return (b & 0x80000000u) ? ~b : (b | 0x80000000u);
}

__device__ __forceinline__ float4 dequant4(int4 q, float s, float z) {
    return make_float4((float)q.x * s + z, (float)q.y * s + z,
                       (float)q.z * s + z, (float)q.w * s + z);
}

// Requantize a dequantized row value set + write q row / scale / zero.
__device__ __forceinline__ void requant_store(const float4 f, float mn, float mx,
                                              float* __restrict__ out,
                                              size_t q_off, size_t s_off,
                                              size_t z_off, int r, int lane)
{
    const float scl = fmaxf((mx - mn) * (1.0f / 15.0f), 1e-6f);
    const float inv = 1.0f / scl;
    float4 qv = make_float4(
        fminf(fmaxf(rintf((f.x - mn) * inv), 0.0f), 15.0f),
        fminf(fmaxf(rintf((f.y - mn) * inv), 0.0f), 15.0f),
        fminf(fmaxf(rintf((f.z - mn) * inv), 0.0f), 15.0f),
        fminf(fmaxf(rintf((f.w - mn) * inv), 0.0f), 15.0f));
    __stcs(reinterpret_cast<float4*>(out + q_off + (size_t)r * 128 + lane * 4), qv);
    if (lane == 0) { out[s_off + r] = scl; out[z_off + r] = mn; }
}

// Patch one evicted row with the new token value (fixup path).
__device__ __forceinline__ void fill_row(const float4 fv, float* __restrict__ out,
                                         size_t kv_off, size_t q_off,
                                         size_t s_off, size_t z_off,
                                         int r, int lane)
{
    *reinterpret_cast<float4*>(out + kv_off + (size_t)r * 128 + lane * 4) = fv;

    float mn = fminf(fminf(fv.x, fv.y), fminf(fv.z, fv.w));
    float mx = fmaxf(fmaxf(fv.x, fv.y), fmaxf(fv.z, fv.w));
    #pragma unroll
    for (int o = 16; o > 0; o >>= 1) {
        mn = fminf(mn, __shfl_xor_sync(0xFFFFFFFFu, mn, o));
        mx = fmaxf(mx, __shfl_xor_sync(0xFFFFFFFFu, mx, o));
    }
    const float scale = fmaxf((mx - mn) * (1.0f / 15.0f), 1e-6f);
    const float inv   = 1.0f / scale;
    float4 qv = make_float4(
        fminf(fmaxf(rintf((fv.x - mn) * inv), 0.0f), 15.0f),
        fminf(fmaxf(rintf((fv.y - mn) * inv), 0.0f), 15.0f),
        fminf(fmaxf(rintf((fv.z - mn) * inv), 0.0f), 15.0f),
        fminf(fmaxf(rintf((fv.w - mn) * inv), 0.0f), 15.0f));
    *reinterpret_cast<float4*>(out + q_off + (size_t)r * 128 + lane * 4) = qv;
    if (lane == 0) { out[s_off + r] = scale; out[z_off + r] = mn; }
}

// ---------------------------------------------------------------------------
// Fused kernel: one warp per row-pair {2w, 2w+1}, handling BOTH K and V rows.
// Single pass + last-block fixup (no second launch).
// ---------------------------------------------------------------------------
__global__ void __launch_bounds__(256)
kv_fused_kernel(const int4* __restrict__ kq, const int4* __restrict__ vq,
                const float* __restrict__ ksc, const float* __restrict__ kze,
                const float* __restrict__ vsc, const float* __restrict__ vze,
                const int* __restrict__ pos, const float* __restrict__ w,
                const int* __restrict__ input_pos,
                const float* __restrict__ kval, const float* __restrict__ vval,
                float* __restrict__ out)
{
    __shared__ unsigned long long s_key[8];
    __shared__ int s_last;

    const int warp = threadIdx.x >> 5;
    const int lane = threadIdx.x & 31;
    const int wi   = blockIdx.x * 8 + warp;     // 0 .. ROWS/2-1
    const int r0   = wi * 2;
    const int r1   = r0 + 1;
    const int h    = r0 >> 13;                  // same head for whole block

    // ---- front-batched loads (4 wide LDG, evict-first) ----
    const int4 a0 = __ldcs(&kq[(size_t)r0 * 32 + lane]);
    const int4 a1 = __ldcs(&kq[(size_t)r1 * 32 + lane]);
    const int4 b0 = __ldcs(&vq[(size_t)r0 * 32 + lane]);
    const int4 b1 = __ldcs(&vq[(size_t)r1 * 32 + lane]);
    const float ks0 = ksc[r0], ks1 = ksc[r1];
    const float kz0 = kze[r0], kz1 = kze[r1];
    const float vs0 = vsc[r0], vs1 = vsc[r1];
    const float vz0 = vze[r0], vz1 = vze[r1];
    const float4 wv =
        *reinterpret_cast<const float4*>(w + (size_t)h * 128 + lane * 4);
    const int p0 = pos[r0];
    const int p1 = pos[r1];

    // ---- dequantize ----
    const float4 k0 = dequant4(a0, ks0, kz0);
    const float4 k1 = dequant4(a1, ks1, kz1);
    const float4 v0 = dequant4(b0, vs0, vz0);
    const float4 v1 = dequant4(b1, vs1, vz1);

    // ---- write dequantized kv (streaming) ----
    const int c = lane * 4;
    __stcs(reinterpret_cast<float4*>(out + OFF_K + (size_t)r0 * 128 + c), k0);
    __stcs(reinterpret_cast<float4*>(out + OFF_K + (size_t)r1 * 128 + c), k1);
    __stcs(reinterpret_cast<float4*>(out + OFF_V + (size_t)r0 * 128 + c), v0);
    __stcs(reinterpret_cast<float4*>(out + OFF_V + (size_t)r1 * 128 + c), v1);

    // ---- row min/max + K scores (combined butterfly) ----
    float mnk0 = fminf(fminf(k0.x, k0.y), fminf(k0.z, k0.w));
    float mxk0 = fmaxf(fmaxf(k0.x, k0.y), fmaxf(k0.z, k0.w));
    float mnk1 = fminf(fminf(k1.x, k1.y), fminf(k1.z, k1.w));
    float mxk1 = fmaxf(fmaxf(k1.x, k1.y), fmaxf(k1.z, k1.w));
    float mnv0 = fminf(fminf(v0.x, v0.y), fminf(v0.z, v0.w));
    float mxv0 = fmaxf(fmaxf(v0.x, v0.y), fmaxf(v0.z, v0.w));
    float mnv1 = fminf(fminf(v1.x, v1.y), fminf(v1.z, v1.w));
    float mxv1 = fmaxf(fmaxf(v1.x, v1.y), fmaxf(v1.z, v1.w));
    float sc0 = k0.x * wv.x + k0.y * wv.y + k0.z * wv.z + k0.w * wv.w;
    float sc1 = k1.x * wv.x + k1.y * wv.y + k1.z * wv.z + k1.w * wv.w;

    #pragma unroll
    for (int o = 16; o > 0; o >>= 1) {
        mnk0 = fminf(mnk0, __shfl_xor_sync(0xFFFFFFFFu, mnk0, o));
        mxk0 = fmaxf(mxk0, __shfl_xor_sync(0xFFFFFFFFu, mxk0, o));
        mnk1 = fminf(mnk1, __shfl_xor_sync(0xFFFFFFFFu, mnk1, o));
        mxk1 = fmaxf(mxk1, __shfl_xor_sync(0xFFFFFFFFu, mxk1, o));
        mnv0 = fminf(mnv0, __shfl_xor_sync(0xFFFFFFFFu, mnv0, o));
        mxv0 = fmaxf(mxv0, __shfl_xor_sync(0xFFFFFFFFu, mxv0, o));
        mnv1 = fminf(mnv1, __shfl_xor_sync(0xFFFFFFFFu, mnv1, o));
        mxv1 = fmaxf(mxv1, __shfl_xor_sync(0xFFFFFFFFu, mxv1, o));
        sc0 += __shfl_xor_sync(0xFFFFFFFFu, sc0, o);
        sc1 += __shfl_xor_sync(0xFFFFFFFFu, sc1, o);
    }

    // ---- requantize + write ----
    requant_store(k0, mnk0, mxk0, out, OFF_KQ, OFF_KS, OFF_KZ, r0, lane);
    requant_store(k1, mnk1, mxk1, out, OFF_KQ, OFF_KS, OFF_KZ, r1, lane);
    requant_store(v0, mnv0, mxv0, out, OFF_VQ, OFF_VS, OFF_VZ, r0, lane);
    requant_store(v1, mnv1, mxv1, out, OFF_VQ, OFF_VS, OFF_VZ, r1, lane);

    // ---- pos_new baseline copy + eviction key ----
    const int l0 = r0 & 8191;
    const int l1 = r1 & 8191;
    float score0 = sc0, score1 = sc1;
    if (l0 < GLOBAL_TOKENS) score0 =  __int_as_float(0x7F800000);
    if (p0 == -1)           score0 = -__int_as_float(0x7F800000);
    if (l1 < GLOBAL_TOKENS) score1 =  __int_as_float(0x7F800000);
    if (p1 == -1)           score1 = -__int_as_float(0x7F800000);

    const unsigned long long key0 =
        ~(((unsigned long long)float_orderable(score0) << 32) | (unsigned int)l0);
    const unsigned long long key1 =
        ~(((unsigned long long)float_orderable(score1) << 32) | (unsigned int)l1);

    if (lane == 0) {
        out[OFF_POS + r0] = (float)p0;
        out[OFF_POS + r1] = (float)p1;
        s_key[warp] = (key0 > key1) ? key0 : key1;   // max of complements
    }
    __syncthreads();

    // One argmax atomic per block; then completion counter (release).
    if (threadIdx.x == 0) {
        unsigned long long m = s_key[0];
        #pragma unroll
        for (int i = 1; i < 8; i++) m = (s_key[i] > m) ? s_key[i] : m;
        atomicMax(&g_argmax[h * 16], m);
        __threadfence();                              // release all prior work
        const unsigned int n = atomicAdd(&g_count, 1u);
        s_last = (n == (unsigned int)(NBLOCKS - 1)) ? 1 : 0;
    }
    __syncthreads();
    if (!s_last) return;

    // =======================================================================
    // Last block: fixup. All other blocks' STGs + argmax atomics are visible
    // (threadfence-release before counter, acquire below).
    // =======================================================================
    __threadfence();                                  // acquire

    // 8 warps handle 32 heads: warp w does heads w, w+8, w+16, w+24.
    #pragma unroll
    for (int i = 0; i < 4; i++) {
        const int hh = warp + i * 8;
        const unsigned long long pk = ~g_argmax[hh * 16];  // (score, idx)
        const int idx = (int)(unsigned int)(pk & 0xFFFFFFFFull);
        const int r   = hh * L_DIM + idx;

        if (lane == 0) {
            out[OFF_NINS + hh] = (pos[r] == -1) ? 1.0f : 0.0f;
            out[OFF_POS + r]   = (float)input_pos[0];
            g_argmax[hh * 16]  = 0ull;                // reset for next replay
        }

        const float4 kf =
            *reinterpret_cast<const float4*>(kval + (size_t)hh * 128 + lane * 4);
        fill_row(kf, out, OFF_K, OFF_KQ, OFF_KS, OFF_KZ, r, lane);

        const float4 vf =
            *reinterpret_cast<const float4*>(vval + (size_t)hh * 128 + lane * 4);
        fill_row(vf, out, OFF_V, OFF_VQ, OFF_VS, OFF_VZ, r, lane);
    }

    if (threadIdx.x == 0) g_count = 0u;               // reset for next replay
}

// ---------------------------------------------------------------------------
// Launch: one kernel, one graph node.
// ---------------------------------------------------------------------------
extern "C" void kernel_launch(void* const* d_in, const int* in_sizes, int n_in,
                              void* d_out, int out_size)
{
    const int4*  kq   = (const int4*) d_in[0];   // k_cache_q  int32
    const int4*  vq   = (const int4*) d_in[1];   // v_cache_q  int32
    const float* ksc  = (const float*)d_in[2];   // k_scales
    const float* kze  = (const float*)d_in[3];   // k_zeros
    const float* vsc  = (const float*)d_in[4];   // v_scales
    const float* vze  = (const float*)d_in[5];   // v_zeros
    const int*   pos  = (const int*)  d_in[6];   // pos        int32
    const int*   ipos = (const int*)  d_in[7];   // input_pos  scalar
    const float* kval = (const float*)d_in[8];   // k_val
    const float* vval = (const float*)d_in[9];   // v_val
    const float* w    = (const float*)d_in[10];  // w
    float* out = (float*)d_out;

    kv_fused_kernel<<<NBLOCKS, 256>>>(kq, vq, ksc, kze, vsc, vze,
                                      pos, w, ipos, kval, vval, out);
}